// round 1
// baseline (speedup 1.0000x reference)
#include <cuda_runtime.h>
#include <math.h>

#define H 2048
#define TPB 256
#define NWARP (TPB / 32)

// Ping-pong buffer for inter-layer hidden state (layer0 -> buf0 -> layer1 -> buf1 -> layer2 -> d_out)
__device__ __align__(16) float g_hbuf[2][H];

__device__ __forceinline__ float dot4(float4 w, float4 v) {
    return w.x * v.x + w.y * v.y + w.z * v.z + w.w * v.w;
}

__device__ __forceinline__ float sigmoidf_(float v) {
    return 1.0f / (1.0f + expf(-v));
}

// One block per output element j. Computes the 4 gate dot products
// (rows j, H+j, 2H+j, 3H+j of both Wi and Wh), applies activations,
// and writes h_new[j]. c_new is consumed in-kernel (never stored).
__global__ void __launch_bounds__(TPB) lstm_layer_kernel(
    const float* __restrict__ Wi,   // [4H, H] this layer
    const float* __restrict__ Wh,   // [4H, H] this layer
    const float* __restrict__ bi,   // [4H]
    const float* __restrict__ bh,   // [4H]
    const float* __restrict__ xin,  // [H] input vector
    const float* __restrict__ hin,  // [H] previous hidden
    const float* __restrict__ cin,  // [H] previous cell
    float* __restrict__ hout)       // [H]
{
    const int j = blockIdx.x;
    const int t = threadIdx.x;

    const float4* __restrict__ x4 = (const float4*)xin;
    const float4* __restrict__ h4 = (const float4*)hin;

    const float4* __restrict__ wi0 = (const float4*)(Wi + (size_t)(0 * H + j) * H);
    const float4* __restrict__ wi1 = (const float4*)(Wi + (size_t)(1 * H + j) * H);
    const float4* __restrict__ wi2 = (const float4*)(Wi + (size_t)(2 * H + j) * H);
    const float4* __restrict__ wi3 = (const float4*)(Wi + (size_t)(3 * H + j) * H);
    const float4* __restrict__ wh0 = (const float4*)(Wh + (size_t)(0 * H + j) * H);
    const float4* __restrict__ wh1 = (const float4*)(Wh + (size_t)(1 * H + j) * H);
    const float4* __restrict__ wh2 = (const float4*)(Wh + (size_t)(2 * H + j) * H);
    const float4* __restrict__ wh3 = (const float4*)(Wh + (size_t)(3 * H + j) * H);

    float a0 = 0.f, a1 = 0.f, a2 = 0.f, a3 = 0.f;

    // H/4 = 512 float4 elements per row; TPB=256 -> exactly 2 iterations/thread.
    #pragma unroll
    for (int k = t; k < H / 4; k += TPB) {
        float4 xv = x4[k];
        float4 hv = h4[k];
        a0 += dot4(wi0[k], xv);
        a1 += dot4(wi1[k], xv);
        a2 += dot4(wi2[k], xv);
        a3 += dot4(wi3[k], xv);
        a0 += dot4(wh0[k], hv);
        a1 += dot4(wh1[k], hv);
        a2 += dot4(wh2[k], hv);
        a3 += dot4(wh3[k], hv);
    }

    // Warp reduction of the 4 accumulators
    #pragma unroll
    for (int off = 16; off > 0; off >>= 1) {
        a0 += __shfl_xor_sync(0xffffffffu, a0, off);
        a1 += __shfl_xor_sync(0xffffffffu, a1, off);
        a2 += __shfl_xor_sync(0xffffffffu, a2, off);
        a3 += __shfl_xor_sync(0xffffffffu, a3, off);
    }

    __shared__ float s[4][NWARP];
    const int warp = t >> 5;
    const int lane = t & 31;
    if (lane == 0) {
        s[0][warp] = a0;
        s[1][warp] = a1;
        s[2][warp] = a2;
        s[3][warp] = a3;
    }
    __syncthreads();

    if (t == 0) {
        float gi = 0.f, gf = 0.f, gg = 0.f, go = 0.f;
        #pragma unroll
        for (int w = 0; w < NWARP; w++) {
            gi += s[0][w];
            gf += s[1][w];
            gg += s[2][w];
            go += s[3][w];
        }
        gi += bi[0 * H + j] + bh[0 * H + j];
        gf += bi[1 * H + j] + bh[1 * H + j];
        gg += bi[2 * H + j] + bh[2 * H + j];
        go += bi[3 * H + j] + bh[3 * H + j];

        float iv = sigmoidf_(gi);
        float fv = sigmoidf_(gf);
        float gv = tanhf(gg);
        float ov = sigmoidf_(go);
        float c_new = fv * cin[j] + iv * gv;
        hout[j] = ov * tanhf(c_new);
    }
}

extern "C" void kernel_launch(void* const* d_in, const int* in_sizes, int n_in,
                              void* d_out, int out_size) {
    (void)in_sizes; (void)n_in;
    const float* x    = (const float*)d_in[0];  // [H]
    const float* W_ih = (const float*)d_in[1];  // [L, 4H, H]
    const float* W_hh = (const float*)d_in[2];  // [L, 4H, H]
    const float* b_ih = (const float*)d_in[3];  // [L, 4H]
    const float* b_hh = (const float*)d_in[4];  // [L, 4H]
    const float* h0   = (const float*)d_in[5];  // [L, H]
    const float* c0   = (const float*)d_in[6];  // [L, H]
    float* out = (float*)d_out;                 // [H]
    (void)out_size;

    float* hbuf;
    cudaGetSymbolAddress((void**)&hbuf, g_hbuf);
    float* hbuf0 = hbuf;
    float* hbuf1 = hbuf + H;

    const size_t Wstride = (size_t)4 * H * H;
    const size_t bstride = (size_t)4 * H;

    // Layer 0: x -> hbuf0
    lstm_layer_kernel<<<H, TPB>>>(W_ih, W_hh, b_ih, b_hh,
                                  x, h0, c0, hbuf0);
    // Layer 1: hbuf0 -> hbuf1
    lstm_layer_kernel<<<H, TPB>>>(W_ih + Wstride, W_hh + Wstride,
                                  b_ih + bstride, b_hh + bstride,
                                  hbuf0, h0 + H, c0 + H, hbuf1);
    // Layer 2: hbuf1 -> d_out
    lstm_layer_kernel<<<H, TPB>>>(W_ih + 2 * Wstride, W_hh + 2 * Wstride,
                                  b_ih + 2 * bstride, b_hh + 2 * bstride,
                                  hbuf1, h0 + 2 * H, c0 + 2 * H, out);
}

// round 3
// speedup vs baseline: 1.0126x; 1.0126x over previous
#include <cuda_runtime.h>
#include <math.h>

#define H 2048
#define TPB 256   // 8 warps = 8 dot-product rows (4 Wi gates + 4 Wh gates)

// Ping-pong buffer for inter-layer hidden state
__device__ __align__(16) float g_hbuf[2][H];

__device__ __forceinline__ float dot4(float4 w, float4 v) {
    return w.x * v.x + w.y * v.y + w.z * v.z + w.w * v.w;
}

__device__ __forceinline__ float sigmoidf_(float v) {
    return 1.0f / (1.0f + __expf(-v));
}

// One block per output element j. Warp w (0..3) computes Wi gate-row w · x,
// warp w (4..7) computes Wh gate-row (w-4) · h. Single shfl reduction per warp,
// tiny smem combine, epilogue on thread 0.
__global__ void __launch_bounds__(TPB, 4) lstm_layer_kernel(
    const float* __restrict__ Wi,   // [4H, H]
    const float* __restrict__ Wh,   // [4H, H]
    const float* __restrict__ bi,   // [4H]
    const float* __restrict__ bh,   // [4H]
    const float* __restrict__ xin,  // [H]
    const float* __restrict__ hin,  // [H]
    const float* __restrict__ cin,  // [H]
    float* __restrict__ hout)       // [H]
{
    const int j    = blockIdx.x;
    const int t    = threadIdx.x;
    const int warp = t >> 5;
    const int lane = t & 31;

    // Row this warp owns (8 KB contiguous stream)
    const float* rowbase = (warp < 4)
        ? (Wi + ((size_t)warp * H + j) * H)
        : (Wh + ((size_t)(warp - 4) * H + j) * H);
    const float4* __restrict__ r4 = (const float4*)rowbase;
    const float4* __restrict__ v4 = (warp < 4) ? (const float4*)xin
                                               : (const float4*)hin;

    // H/4 = 512 float4 per row; 32 lanes -> 16 float4 per lane. Fully unrolled,
    // 4 independent accumulators -> deep MLP on the streaming weight loads.
    float a0 = 0.f, a1 = 0.f, a2 = 0.f, a3 = 0.f;
    #pragma unroll
    for (int i = 0; i < 16; i += 4) {
        float4 w0 = __ldcs(&r4[(i + 0) * 32 + lane]);
        float4 w1 = __ldcs(&r4[(i + 1) * 32 + lane]);
        float4 w2 = __ldcs(&r4[(i + 2) * 32 + lane]);
        float4 w3 = __ldcs(&r4[(i + 3) * 32 + lane]);
        float4 v0 = v4[(i + 0) * 32 + lane];
        float4 v1 = v4[(i + 1) * 32 + lane];
        float4 v2 = v4[(i + 2) * 32 + lane];
        float4 v3 = v4[(i + 3) * 32 + lane];
        a0 += dot4(w0, v0);
        a1 += dot4(w1, v1);
        a2 += dot4(w2, v2);
        a3 += dot4(w3, v3);
    }
    float a = (a0 + a1) + (a2 + a3);

    // Intra-warp reduce
    #pragma unroll
    for (int off = 16; off > 0; off >>= 1)
        a += __shfl_xor_sync(0xffffffffu, a, off);

    __shared__ float s[8];
    if (lane == 0) s[warp] = a;
    __syncthreads();

    if (t == 0) {
        float gi = s[0] + s[4] + bi[0 * H + j] + bh[0 * H + j];
        float gf = s[1] + s[5] + bi[1 * H + j] + bh[1 * H + j];
        float gg = s[2] + s[6] + bi[2 * H + j] + bh[2 * H + j];
        float go = s[3] + s[7] + bi[3 * H + j] + bh[3 * H + j];

        float iv = sigmoidf_(gi);
        float fv = sigmoidf_(gf);
        float gv = tanhf(gg);
        float ov = sigmoidf_(go);
        float c_new = fv * cin[j] + iv * gv;
        hout[j] = ov * tanhf(c_new);
    }
}

extern "C" void kernel_launch(void* const* d_in, const int* in_sizes, int n_in,
                              void* d_out, int out_size) {
    (void)in_sizes; (void)n_in; (void)out_size;
    const float* x    = (const float*)d_in[0];  // [H]
    const float* W_ih = (const float*)d_in[1];  // [L, 4H, H]
    const float* W_hh = (const float*)d_in[2];  // [L, 4H, H]
    const float* b_ih = (const float*)d_in[3];  // [L, 4H]
    const float* b_hh = (const float*)d_in[4];  // [L, 4H]
    const float* h0   = (const float*)d_in[5];  // [L, H]
    const float* c0   = (const float*)d_in[6];  // [L, H]
    float* out = (float*)d_out;                 // [H]

    float* hbuf;
    cudaGetSymbolAddress((void**)&hbuf, g_hbuf);
    float* hbuf0 = hbuf;
    float* hbuf1 = hbuf + H;

    const size_t Wstride = (size_t)4 * H * H;
    const size_t bstride = (size_t)4 * H;

    lstm_layer_kernel<<<H, TPB>>>(W_ih, W_hh, b_ih, b_hh,
                                  x, h0, c0, hbuf0);
    lstm_layer_kernel<<<H, TPB>>>(W_ih + Wstride, W_hh + Wstride,
                                  b_ih + bstride, b_hh + bstride,
                                  hbuf0, h0 + H, c0 + H, hbuf1);
    lstm_layer_kernel<<<H, TPB>>>(W_ih + 2 * Wstride, W_hh + 2 * Wstride,
                                  b_ih + 2 * bstride, b_hh + 2 * bstride,
                                  hbuf1, h0 + 2 * H, c0 + 2 * H, out);
}